// round 15
// baseline (speedup 1.0000x reference)
#include <cuda_runtime.h>
#include <math.h>

// Geometry: 64 images of 512*512*3 = 786432 floats (3 MB each)
#define N_IMG 64
#define IMG_ELEMS 786432
#define IMG_VEC4  196608                 // IMG_ELEMS / 4

#define GROUPS 8
#define IMG_PER_GRP 8                    // 24 MB/group; residue+fill = 48 MB << 126 MB L2

// Reduce shape (per group)
#define BLOCKS_PER_IMG 48
#define CHUNK_VEC4 (IMG_VEC4 / BLOCKS_PER_IMG)          // 4096
#define RED_THREADS 256
#define RED_BLOCKS (IMG_PER_GRP * BLOCKS_PER_IMG)       // 384 (2.6/SM, balanced)

// Apply shape (per group)
#define APPLY_THREADS 256
#define V4_PER_THREAD 4
#define V4_PER_BLOCK (APPLY_THREADS * V4_PER_THREAD)    // 1024
#define APPLY_BLOCKS_PER_IMG (IMG_VEC4 / V4_PER_BLOCK)  // 192
#define APPLY_BLOCKS (IMG_PER_GRP * APPLY_BLOCKS_PER_IMG) // 1536

// Scratch (no allocations allowed)
__device__ float2 g_partials[N_IMG * BLOCKS_PER_IMG];

// -------- Reduce one group: per-chunk (sum, sumsq); fills L2 with the group --------
// With PDL, this launch overlaps the previous group's apply.
__global__ __launch_bounds__(RED_THREADS)
void partial_reduce_kernel(const float4* __restrict__ in, int grp) {
    const int limg  = blockIdx.x / BLOCKS_PER_IMG;
    const int chunk = blockIdx.x % BLOCKS_PER_IMG;
    const int img   = grp * IMG_PER_GRP + limg;
    const float4* __restrict__ p =
        in + (size_t)img * IMG_VEC4 + (size_t)chunk * CHUNK_VEC4;

    float s = 0.f, sq = 0.f;
    #pragma unroll 8
    for (int i = threadIdx.x; i < CHUNK_VEC4; i += RED_THREADS) {
        float4 v = __ldcg(p + i);          // evict-normal in L2: apply re-reads it
        s  += (v.x + v.y) + (v.z + v.w);
        sq += (v.x * v.x + v.y * v.y) + (v.z * v.z + v.w * v.w);
    }

    #pragma unroll
    for (int off = 16; off > 0; off >>= 1) {
        s  += __shfl_down_sync(0xffffffffu, s,  off);
        sq += __shfl_down_sync(0xffffffffu, sq, off);
    }
    __shared__ float2 warp_red[RED_THREADS / 32];
    const int lane = threadIdx.x & 31, wid = threadIdx.x >> 5;
    if (lane == 0) warp_red[wid] = make_float2(s, sq);
    __syncthreads();
    if (wid == 0) {
        float2 v = (lane < RED_THREADS / 32) ? warp_red[lane] : make_float2(0.f, 0.f);
        s = v.x; sq = v.y;
        #pragma unroll
        for (int off = 4; off > 0; off >>= 1) {
            s  += __shfl_down_sync(0xffffffffu, s,  off);
            sq += __shfl_down_sync(0xffffffffu, sq, off);
        }
        if (lane == 0) g_partials[img * BLOCKS_PER_IMG + chunk] = make_float2(s, sq);
    }
}

// -------- Apply one group --------
// Trigger at entry releases the NEXT reduce launch (independent -> overlap).
// Grid-dependency sync before loads guarantees reduce(g)'s partials are
// visible AND the group's lines are still L2-resident.
__global__ __launch_bounds__(APPLY_THREADS)
void apply_kernel(const float4* __restrict__ in, float4* __restrict__ out, int grp) {
    cudaTriggerProgrammaticLaunchCompletion();
    cudaGridDependencySynchronize();

    const int limg = blockIdx.x / APPLY_BLOCKS_PER_IMG;
    const int img  = grp * IMG_PER_GRP + limg;
    const size_t base = (size_t)img * IMG_VEC4 +
                        (size_t)(blockIdx.x % APPLY_BLOCKS_PER_IMG) * V4_PER_BLOCK +
                        threadIdx.x;

    // Front-batch loads: mostly L2 hits; .cs marks lines dead after read.
    float4 v[V4_PER_THREAD];
    #pragma unroll
    for (int k = 0; k < V4_PER_THREAD; ++k)
        v[k] = __ldcs(in + base + k * APPLY_THREADS);

    // Inline finalize: warp 0 reduces this image's 48 partials.
    // Fixed summation order -> deterministic, identical across all blocks.
    __shared__ float2 sh_ss;
    if (threadIdx.x < 32) {
        const int lane = threadIdx.x;
        float2 p = g_partials[img * BLOCKS_PER_IMG + lane];
        float s = p.x, sq = p.y;
        if (lane < BLOCKS_PER_IMG - 32) {
            float2 q = g_partials[img * BLOCKS_PER_IMG + 32 + lane];
            s += q.x; sq += q.y;
        }
        #pragma unroll
        for (int off = 16; off > 0; off >>= 1) {
            s  += __shfl_down_sync(0xffffffffu, s,  off);
            sq += __shfl_down_sync(0xffffffffu, sq, off);
        }
        if (lane == 0) {
            const float inv_n = 1.0f / (float)IMG_ELEMS;
            float mean = s * inv_n;
            float var  = sq * inv_n - mean * mean;
            float stddev = sqrtf(fmaxf(var, 0.0f));
            const float min_std = 1.0f / sqrtf((float)IMG_ELEMS);
            float scale = 1.0f / fmaxf(stddev, min_std);
            sh_ss = make_float2(scale, -mean * scale);
        }
    }
    __syncthreads();
    const float scale = sh_ss.x, shift = sh_ss.y;

    #pragma unroll
    for (int k = 0; k < V4_PER_THREAD; ++k) {
        float4 r;
        r.x = fmaf(v[k].x, scale, shift);
        r.y = fmaf(v[k].y, scale, shift);
        r.z = fmaf(v[k].z, scale, shift);
        r.w = fmaf(v[k].w, scale, shift);
        __stcs(out + base + k * APPLY_THREADS, r);   // evict-first: spare the residue
    }
}

extern "C" void kernel_launch(void* const* d_in, const int* in_sizes, int n_in,
                              void* d_out, int out_size) {
    const float4* in = (const float4*)d_in[0];
    float4* out = (float4*)d_out;

    cudaLaunchAttribute attr[1];
    attr[0].id = cudaLaunchAttributeProgrammaticStreamSerialization;
    attr[0].val.programmaticStreamSerializationAllowed = 1;

    cudaLaunchConfig_t rcfg = {};
    rcfg.gridDim  = dim3(RED_BLOCKS, 1, 1);
    rcfg.blockDim = dim3(RED_THREADS, 1, 1);
    rcfg.attrs = attr; rcfg.numAttrs = 1;

    cudaLaunchConfig_t acfg = {};
    acfg.gridDim  = dim3(APPLY_BLOCKS, 1, 1);
    acfg.blockDim = dim3(APPLY_THREADS, 1, 1);
    acfg.attrs = attr; acfg.numAttrs = 1;

    for (int g = 0; g < GROUPS; ++g) {
        cudaLaunchKernelEx(&rcfg, partial_reduce_kernel, in, g);
        cudaLaunchKernelEx(&acfg, apply_kernel, in, out, g);
    }
}

// round 16
// speedup vs baseline: 1.1239x; 1.1239x over previous
#include <cuda_runtime.h>
#include <math.h>

// Geometry: 64 images of 512*512*3 = 786432 floats (3 MB each)
#define N_IMG 64
#define IMG_ELEMS 786432
#define IMG_VEC4  196608                 // IMG_ELEMS / 4

// Asymmetric pipeline: small end groups (shorter non-overlapped head/tail),
// large middle groups (fewer pair overheads). L2 coexistence (residue+fill)
// worst case = 16+16 images = 96 MB < 126 MB.
#define N_GRP 5
static const int GRP_OFF[N_GRP] = {0, 8, 24, 40, 56};
static const int GRP_CNT[N_GRP] = {8, 16, 16, 16, 8};

// Reduce shape
#define BLOCKS_PER_IMG 48
#define CHUNK_VEC4 (IMG_VEC4 / BLOCKS_PER_IMG)          // 4096
#define RED_THREADS 256

// Apply shape
#define APPLY_THREADS 256
#define V4_PER_THREAD 4
#define V4_PER_BLOCK (APPLY_THREADS * V4_PER_THREAD)    // 1024
#define APPLY_BLOCKS_PER_IMG (IMG_VEC4 / V4_PER_BLOCK)  // 192

// Scratch (no allocations allowed)
__device__ float2 g_partials[N_IMG * BLOCKS_PER_IMG];

// -------- Reduce one group: per-chunk (sum, sumsq); fills L2 with the group --------
// With PDL, this launch overlaps the previous group's apply.
__global__ __launch_bounds__(RED_THREADS)
void partial_reduce_kernel(const float4* __restrict__ in, int img_off) {
    const int limg  = blockIdx.x / BLOCKS_PER_IMG;
    const int chunk = blockIdx.x % BLOCKS_PER_IMG;
    const int img   = img_off + limg;
    const float4* __restrict__ p =
        in + (size_t)img * IMG_VEC4 + (size_t)chunk * CHUNK_VEC4;

    float s = 0.f, sq = 0.f;
    #pragma unroll 8
    for (int i = threadIdx.x; i < CHUNK_VEC4; i += RED_THREADS) {
        float4 v = __ldcg(p + i);          // evict-normal in L2: apply re-reads it
        s  += (v.x + v.y) + (v.z + v.w);
        sq += (v.x * v.x + v.y * v.y) + (v.z * v.z + v.w * v.w);
    }

    #pragma unroll
    for (int off = 16; off > 0; off >>= 1) {
        s  += __shfl_down_sync(0xffffffffu, s,  off);
        sq += __shfl_down_sync(0xffffffffu, sq, off);
    }
    __shared__ float2 warp_red[RED_THREADS / 32];
    const int lane = threadIdx.x & 31, wid = threadIdx.x >> 5;
    if (lane == 0) warp_red[wid] = make_float2(s, sq);
    __syncthreads();
    if (wid == 0) {
        float2 v = (lane < RED_THREADS / 32) ? warp_red[lane] : make_float2(0.f, 0.f);
        s = v.x; sq = v.y;
        #pragma unroll
        for (int off = 4; off > 0; off >>= 1) {
            s  += __shfl_down_sync(0xffffffffu, s,  off);
            sq += __shfl_down_sync(0xffffffffu, sq, off);
        }
        if (lane == 0) g_partials[img * BLOCKS_PER_IMG + chunk] = make_float2(s, sq);
    }
}

// -------- Apply one group --------
// Trigger at entry releases the NEXT reduce launch (independent -> overlap).
// Grid-dependency sync before loads guarantees reduce(g)'s partials are
// visible AND the group's lines are still L2-resident.
__global__ __launch_bounds__(APPLY_THREADS)
void apply_kernel(const float4* __restrict__ in, float4* __restrict__ out, int img_off) {
    cudaTriggerProgrammaticLaunchCompletion();
    cudaGridDependencySynchronize();

    const int limg = blockIdx.x / APPLY_BLOCKS_PER_IMG;
    const int img  = img_off + limg;
    const size_t base = (size_t)img * IMG_VEC4 +
                        (size_t)(blockIdx.x % APPLY_BLOCKS_PER_IMG) * V4_PER_BLOCK +
                        threadIdx.x;

    // Front-batch loads: mostly L2 hits; .cs marks lines dead after read.
    float4 v[V4_PER_THREAD];
    #pragma unroll
    for (int k = 0; k < V4_PER_THREAD; ++k)
        v[k] = __ldcs(in + base + k * APPLY_THREADS);

    // Inline finalize: warp 0 reduces this image's 48 partials.
    // Fixed summation order -> deterministic, identical across all blocks.
    __shared__ float2 sh_ss;
    if (threadIdx.x < 32) {
        const int lane = threadIdx.x;
        float2 p = g_partials[img * BLOCKS_PER_IMG + lane];
        float s = p.x, sq = p.y;
        {
            float2 q = g_partials[img * BLOCKS_PER_IMG + 32 + ((lane < 16) ? lane : lane - 16)];
            // lanes 0..15 add partials 32..47; lanes 16..31 would double-count,
            // so mask them out:
            if (lane < 16) { s += q.x; sq += q.y; }
        }
        #pragma unroll
        for (int off = 16; off > 0; off >>= 1) {
            s  += __shfl_down_sync(0xffffffffu, s,  off);
            sq += __shfl_down_sync(0xffffffffu, sq, off);
        }
        if (lane == 0) {
            const float inv_n = 1.0f / (float)IMG_ELEMS;
            float mean = s * inv_n;
            float var  = sq * inv_n - mean * mean;
            float stddev = sqrtf(fmaxf(var, 0.0f));
            const float min_std = 1.0f / sqrtf((float)IMG_ELEMS);
            float scale = 1.0f / fmaxf(stddev, min_std);
            sh_ss = make_float2(scale, -mean * scale);
        }
    }
    __syncthreads();
    const float scale = sh_ss.x, shift = sh_ss.y;

    #pragma unroll
    for (int k = 0; k < V4_PER_THREAD; ++k) {
        float4 r;
        r.x = fmaf(v[k].x, scale, shift);
        r.y = fmaf(v[k].y, scale, shift);
        r.z = fmaf(v[k].z, scale, shift);
        r.w = fmaf(v[k].w, scale, shift);
        __stcs(out + base + k * APPLY_THREADS, r);   // evict-first: spare the residue
    }
}

extern "C" void kernel_launch(void* const* d_in, const int* in_sizes, int n_in,
                              void* d_out, int out_size) {
    const float4* in = (const float4*)d_in[0];
    float4* out = (float4*)d_out;

    cudaLaunchAttribute attr[1];
    attr[0].id = cudaLaunchAttributeProgrammaticStreamSerialization;
    attr[0].val.programmaticStreamSerializationAllowed = 1;

    for (int g = 0; g < N_GRP; ++g) {
        const int off = GRP_OFF[g], cnt = GRP_CNT[g];

        cudaLaunchConfig_t rcfg = {};
        rcfg.gridDim  = dim3(cnt * BLOCKS_PER_IMG, 1, 1);
        rcfg.blockDim = dim3(RED_THREADS, 1, 1);
        rcfg.attrs = attr; rcfg.numAttrs = 1;
        cudaLaunchKernelEx(&rcfg, partial_reduce_kernel, in, off);

        cudaLaunchConfig_t acfg = {};
        acfg.gridDim  = dim3(cnt * APPLY_BLOCKS_PER_IMG, 1, 1);
        acfg.blockDim = dim3(APPLY_THREADS, 1, 1);
        acfg.attrs = attr; acfg.numAttrs = 1;
        cudaLaunchKernelEx(&acfg, apply_kernel, in, out, off);
    }
}